// round 4
// baseline (speedup 1.0000x reference)
#include <cuda_runtime.h>
#include <cuda_bf16.h>
#include <math.h>

// Problem constants (fixed by the dataset)
#define NN 500000
#define EE 8000000
#define IN_DIM 128
#define H1 32
#define H2 16
#define SCAN_BLK 1024
#define NB_SCAN ((NN + SCAN_BLK - 1) / SCAN_BLK)   // 489

// Scratch (device globals; no cudaMalloc allowed)
__device__ float g_A[NN * H1];        // y1 = (x@W1)*dinv
__device__ float g_B[NN * H1];        // h1 = relu(agg1*dinv + b1)
__device__ float g_C[NN * H2];        // y2 = (h1@W2)*dinv
__device__ int   g_src[EE];
__device__ int   g_dst[EE];
__device__ int   g_eidx[EE];          // CSR: src ids grouped by dst
__device__ int   g_cnt[NN];           // edge in-degree (no self loop)
__device__ int   g_cur[NN];           // fill cursors
__device__ int   g_scan[NN];          // per-block inclusive scan of cnt
__device__ int   g_bsum[NB_SCAN];     // block totals
__device__ int   g_boff[NB_SCAN];     // exclusive scan of block totals
__device__ int   g_rowstart[NN + 1];
__device__ float g_dinv[NN];

// ---------------- init / edge prep ----------------

__global__ void k_init(int n) {
    int i = blockIdx.x * blockDim.x + threadIdx.x;
    if (i < n) { g_cnt[i] = 0; g_cur[i] = 0; }
}

// edge_index is int32 (JAX default x64-disabled downcasts the int64 request).
// Bounds-guard defensively: a bad dtype hypothesis must give a wrong answer,
// not a sticky device trap.
__global__ void k_edge_prep(const int* __restrict__ ei, int e, int n) {
    int i = blockIdx.x * blockDim.x + threadIdx.x;
    if (i >= e) return;
    int s = ei[i];
    int d = ei[(size_t)e + i];
    if ((unsigned)s >= (unsigned)n) s = 0;
    if ((unsigned)d >= (unsigned)n) d = 0;
    g_src[i] = s;
    g_dst[i] = d;
    atomicAdd(&g_cnt[d], 1);
}

// ---------------- two-level exclusive scan of g_cnt -> g_rowstart -----------

__global__ void k_scan_a(int n) {
    __shared__ int s[SCAN_BLK];
    int t = threadIdx.x;
    int i = blockIdx.x * SCAN_BLK + t;
    int v = (i < n) ? g_cnt[i] : 0;
    s[t] = v;
    __syncthreads();
    #pragma unroll
    for (int off = 1; off < SCAN_BLK; off <<= 1) {
        int tv = (t >= off) ? s[t - off] : 0;
        __syncthreads();
        s[t] += tv;
        __syncthreads();
    }
    if (i < n) g_scan[i] = s[t];
    if (t == SCAN_BLK - 1) g_bsum[blockIdx.x] = s[t];
}

__global__ void k_scan_b(int nb) {
    __shared__ int s[SCAN_BLK];
    int t = threadIdx.x;
    int v = (t < nb) ? g_bsum[t] : 0;
    s[t] = v;
    __syncthreads();
    #pragma unroll
    for (int off = 1; off < SCAN_BLK; off <<= 1) {
        int tv = (t >= off) ? s[t - off] : 0;
        __syncthreads();
        s[t] += tv;
        __syncthreads();
    }
    if (t < nb) g_boff[t] = s[t] - v;   // exclusive
}

__global__ void k_scan_c(int n, int e) {
    int i = blockIdx.x * blockDim.x + threadIdx.x;
    if (i < n) {
        int cnt = g_cnt[i];
        g_rowstart[i] = g_scan[i] - cnt + g_boff[i / SCAN_BLK];  // exclusive
        g_dinv[i] = rsqrtf((float)(cnt + 1));                    // +1 self loop
    }
    if (i == 0) g_rowstart[n] = e;
}

__global__ void k_fill(int e) {
    int i = blockIdx.x * blockDim.x + threadIdx.x;
    if (i >= e) return;
    int d = g_dst[i];
    int pos = g_rowstart[d] + atomicAdd(&g_cur[d], 1);
    g_eidx[pos] = g_src[i];
}

// ---------------- GEMM1: g_A = (x @ W1) * dinv[row] -------------------------

// block: 256 threads, tile 64 rows x 32 cols, K=128
__global__ void k_gemm1(const float* __restrict__ x, const float* __restrict__ W1, int n) {
    __shared__ float ws[IN_DIM * H1];      // 16 KB
    __shared__ float xs[64 * 132];         // padded rows to dodge conflicts
    const int t = threadIdx.x;
    const int row0 = blockIdx.x * 64;

    {   // W1: 128x32 = 1024 float4
        const float4* w4 = (const float4*)W1;
        float4* s4 = (float4*)ws;
        #pragma unroll
        for (int i = t; i < 1024; i += 256) s4[i] = w4[i];
    }
    {   // x tile: 64 rows x 32 float4
        const float4* x4 = (const float4*)x;
        #pragma unroll
        for (int i = t; i < 2048; i += 256) {
            int r = i >> 5, c = i & 31;
            float4 v = make_float4(0.f, 0.f, 0.f, 0.f);
            if (row0 + r < n) v = x4[(size_t)(row0 + r) * 32 + c];
            *(float4*)(&xs[r * 132 + c * 4]) = v;
        }
    }
    __syncthreads();

    const int tc = t & 7;    // cols 4*tc..4*tc+3
    const int tr = t >> 3;   // rows tr, tr+32
    float acc0[4] = {0.f, 0.f, 0.f, 0.f};
    float acc1[4] = {0.f, 0.f, 0.f, 0.f};
    const float* xpa = &xs[tr * 132];
    const float* xpb = &xs[(tr + 32) * 132];

    #pragma unroll 8
    for (int k = 0; k < IN_DIM; k++) {
        float xa = xpa[k];
        float xb = xpb[k];
        float4 w = *(const float4*)(&ws[k * H1 + tc * 4]);
        acc0[0] += xa * w.x; acc0[1] += xa * w.y; acc0[2] += xa * w.z; acc0[3] += xa * w.w;
        acc1[0] += xb * w.x; acc1[1] += xb * w.y; acc1[2] += xb * w.z; acc1[3] += xb * w.w;
    }

    float4* A4 = (float4*)g_A;
    int r0 = row0 + tr;
    if (r0 < n) {
        float dv = g_dinv[r0];
        A4[(size_t)r0 * 8 + tc] =
            make_float4(acc0[0] * dv, acc0[1] * dv, acc0[2] * dv, acc0[3] * dv);
    }
    int r1 = row0 + tr + 32;
    if (r1 < n) {
        float dv = g_dinv[r1];
        A4[(size_t)r1 * 8 + tc] =
            make_float4(acc1[0] * dv, acc1[1] * dv, acc1[2] * dv, acc1[3] * dv);
    }
}

// ---------------- gather1: h1 = relu((y1[node] + sum y1[nbr]) * dinv + b1) --
// warp per node, lane = channel (H1 = 32)

__global__ void k_gather1(const float* __restrict__ b1, int n) {
    int node = blockIdx.x * (blockDim.x >> 5) + (threadIdx.x >> 5);
    if (node >= n) return;
    int lane = threadIdx.x & 31;
    int beg = g_rowstart[node], end = g_rowstart[node + 1];

    float a0 = g_A[(size_t)node * H1 + lane];   // self loop
    float a1 = 0.f, a2 = 0.f, a3 = 0.f;
    int j = beg;
    for (; j + 4 <= end; j += 4) {
        int s0 = g_eidx[j], s1 = g_eidx[j + 1], s2 = g_eidx[j + 2], s3 = g_eidx[j + 3];
        a0 += g_A[(size_t)s0 * H1 + lane];
        a1 += g_A[(size_t)s1 * H1 + lane];
        a2 += g_A[(size_t)s2 * H1 + lane];
        a3 += g_A[(size_t)s3 * H1 + lane];
    }
    for (; j < end; j++) a0 += g_A[(size_t)g_eidx[j] * H1 + lane];

    float acc = (a0 + a1) + (a2 + a3);
    float dv = g_dinv[node];
    g_B[(size_t)node * H1 + lane] = fmaxf(acc * dv + b1[lane], 0.f);
}

// ---------------- GEMM2: g_C = (h1 @ W2) * dinv  (thread per node) ----------

__global__ void k_gemm2(const float* __restrict__ W2, int n) {
    __shared__ float w2s[H1 * H2];
    int t = threadIdx.x;
    for (int i = t; i < H1 * H2; i += blockDim.x) w2s[i] = W2[i];
    __syncthreads();

    int node = blockIdx.x * blockDim.x + t;
    if (node >= n) return;

    float h[H1];
    {
        const float4* a4 = (const float4*)g_B;
        #pragma unroll
        for (int q = 0; q < 8; q++) {
            float4 v = a4[(size_t)node * 8 + q];
            h[q * 4 + 0] = v.x; h[q * 4 + 1] = v.y; h[q * 4 + 2] = v.z; h[q * 4 + 3] = v.w;
        }
    }
    float acc[H2];
    #pragma unroll
    for (int jj = 0; jj < H2; jj++) acc[jj] = 0.f;
    #pragma unroll
    for (int k = 0; k < H1; k++) {
        float hk = h[k];
        #pragma unroll
        for (int jj = 0; jj < 4; jj++) {
            float4 w = *(const float4*)(&w2s[k * H2 + jj * 4]);
            acc[jj * 4 + 0] += hk * w.x;
            acc[jj * 4 + 1] += hk * w.y;
            acc[jj * 4 + 2] += hk * w.z;
            acc[jj * 4 + 3] += hk * w.w;
        }
    }
    float dv = g_dinv[node];
    float4* C4 = (float4*)g_C;
    #pragma unroll
    for (int jj = 0; jj < 4; jj++)
        C4[(size_t)node * 4 + jj] =
            make_float4(acc[jj * 4 + 0] * dv, acc[jj * 4 + 1] * dv,
                        acc[jj * 4 + 2] * dv, acc[jj * 4 + 3] * dv);
}

// ---------------- gather2 + relu + FC + log_softmax -------------------------
// 16 lanes per node (H2 = 16), 2 nodes per warp. No early return: keep the
// warp converged for the shuffles.

__global__ void k_gather2_final(const float* __restrict__ b2,
                                const float* __restrict__ Wfc,
                                const float* __restrict__ bfc,
                                float* __restrict__ out, int n) {
    int grp  = blockIdx.x * (blockDim.x >> 4) + (threadIdx.x >> 4);
    int lane = threadIdx.x & 15;
    bool valid = (grp < n);
    int node = valid ? grp : 0;

    int beg = g_rowstart[node], end = g_rowstart[node + 1];
    if (!valid) { beg = 0; end = 0; }

    float acc = valid ? g_C[(size_t)node * H2 + lane] : 0.f;
    float a1 = 0.f;
    int j = beg;
    for (; j + 2 <= end; j += 2) {
        int s0 = g_eidx[j], s1 = g_eidx[j + 1];
        acc += g_C[(size_t)s0 * H2 + lane];
        a1  += g_C[(size_t)s1 * H2 + lane];
    }
    for (; j < end; j++) acc += g_C[(size_t)g_eidx[j] * H2 + lane];
    acc += a1;

    float dv = g_dinv[node];
    float h = fmaxf(acc * dv + b2[lane], 0.f);
    float2 w = ((const float2*)Wfc)[lane];   // Wfc row-major [16,2]
    float p0 = h * w.x;
    float p1 = h * w.y;
    // reduce over the 16-lane segment
    #pragma unroll
    for (int off = 8; off >= 1; off >>= 1) {
        p0 += __shfl_xor_sync(0xffffffffu, p0, off, 16);
        p1 += __shfl_xor_sync(0xffffffffu, p1, off, 16);
    }
    if (valid && lane == 0) {
        float l0 = p0 + bfc[0];
        float l1 = p1 + bfc[1];
        float m = fmaxf(l0, l1);
        float lse = m + logf(expf(l0 - m) + expf(l1 - m));
        ((float2*)out)[node] = make_float2(l0 - lse, l1 - lse);
    }
}

// ---------------- launch -----------------------------------------------------

extern "C" void kernel_launch(void* const* d_in, const int* in_sizes, int n_in,
                              void* d_out, int out_size) {
    const float* x   = (const float*)d_in[0];
    const int*   ei  = (const int*)d_in[1];     // int32! (JAX default x64 off)
    const float* W1  = (const float*)d_in[2];
    const float* b1  = (const float*)d_in[3];
    const float* W2  = (const float*)d_in[4];
    const float* b2  = (const float*)d_in[5];
    const float* Wfc = (const float*)d_in[6];
    const float* bfc = (const float*)d_in[7];
    float* out = (float*)d_out;

    const int n = in_sizes[0] / IN_DIM;   // 500000
    const int e = in_sizes[1] / 2;        // 8000000
    const int nb = (n + SCAN_BLK - 1) / SCAN_BLK;

    const int T = 256;
    k_init<<<(n + T - 1) / T, T>>>(n);
    k_edge_prep<<<(e + T - 1) / T, T>>>(ei, e, n);

    k_scan_a<<<nb, SCAN_BLK>>>(n);
    k_scan_b<<<1, SCAN_BLK>>>(nb);
    k_scan_c<<<(n + T - 1) / T, T>>>(n, e);
    k_fill<<<(e + T - 1) / T, T>>>(e);

    k_gemm1<<<(n + 63) / 64, 256>>>(x, W1, n);

    k_gather1<<<(n * 32 + T - 1) / T, T>>>(b1, n);

    k_gemm2<<<(n + T - 1) / T, T>>>(W2, n);

    k_gather2_final<<<(n * 16 + T - 1) / T, T>>>(b2, Wfc, bfc, out, n);
}